// round 6
// baseline (speedup 1.0000x reference)
#include <cuda_runtime.h>
#include <cuda_bf16.h>

// Problem constants (fixed): B=8, T=128, U=64, V=512
#define Bc  8
#define Tc  128
#define Uc  64
#define U1c 65
#define Vc  512
#define NEGV  -1e30f
#define LOG2E 1.4426950408889634f
#define LN2F  0.6931471805599453f

// ------------------------------------------------------------------
// Scratch (device globals)
// ------------------------------------------------------------------
__device__ __align__(16) float g_expP[Bc * U1c * Vc];
__device__ float g_Mu[Bc * U1c];
__device__ float g_pb0[Bc * U1c];
__device__ float g_plab[Bc * Uc];
__device__ __align__(16) float g_BL[Bc * Tc * U1c];  // blank lp, LOG2 domain, stride 65
__device__ __align__(16) float g_LB[Bc * Tc * U1c];  // label lp, LOG2 domain, stride 65 (col 64 unused)
__device__ float g_cost[Bc];
__device__ unsigned int g_bcnt[Bc];   // zero-init; reset each run
__device__ unsigned int g_ticket;     // zero-init; reset each run

__device__ __forceinline__ float lse2(float x, float y)   // log2 domain
{
    float m = fmaxf(x, y);
    return m + __log2f(1.0f + exp2f(-fabsf(x - y)));
}
__device__ __forceinline__ float lse3(float x, float y, float z)
{
    float m = fmaxf(fmaxf(x, y), z);
    return m + __log2f(exp2f(x - m) + exp2f(y - m) + exp2f(z - m));
}

// ------------------------------------------------------------------
// K1: pred rows: rowmax + exp(x-max), Mu/pb0/plab gathers
// ------------------------------------------------------------------
__global__ void k_prep_pred(const float* __restrict__ pred,
                            const int*   __restrict__ labels)
{
    int idx = blockIdx.x;                  // [0, Bc*U1c)
    const float* row = pred + (size_t)idx * Vc;
    float* erow = g_expP + (size_t)idx * Vc;

    int tid = threadIdx.x;                 // 128 threads, 4 floats each
    float4 v = ((const float4*)row)[tid];

    float m = fmaxf(fmaxf(v.x, v.y), fmaxf(v.z, v.w));
#pragma unroll
    for (int o = 16; o; o >>= 1)
        m = fmaxf(m, __shfl_xor_sync(0xffffffffu, m, o));

    __shared__ float sm[4];
    if ((tid & 31) == 0) sm[tid >> 5] = m;
    __syncthreads();
    m = fmaxf(fmaxf(sm[0], sm[1]), fmaxf(sm[2], sm[3]));

    float4 e;
    e.x = __expf(v.x - m);
    e.y = __expf(v.y - m);
    e.z = __expf(v.z - m);
    e.w = __expf(v.w - m);
    ((float4*)erow)[tid] = e;

    if (tid == 0) {
        g_Mu[idx]  = m;
        g_pb0[idx] = v.x;                  // row[0]
        int b = idx / U1c, u = idx % U1c;
        if (u < Uc) {
            int l = labels[b * Uc + u];
            g_plab[b * Uc + u] = row[l];
        }
    }
}

// ------------------------------------------------------------------
// K2 (fused): joint + chained DP. Grid (Tc/2, Bc), 256 threads.
//  Phase A: exp of this block's 2 trans rows into dyn smem (4 KB).
//  Phase B: each warp privately owns its u columns -> BL/LB (no barriers,
//           a-operands fit in 8 float4 regs -> no spills).
//  Phase C: LAST block of batch b runs the alpha DP (single warp,
//           systolic, balanced columns) + final batch sum.
// ------------------------------------------------------------------
__global__ void __launch_bounds__(256)
k_main(const float* __restrict__ trans,
       const int*   __restrict__ labels,
       const int*   __restrict__ act_lens,
       const int*   __restrict__ label_lens,
       float*       __restrict__ out)
{
    extern __shared__ float dsmem[];       // A/B: sexp[2*512]; C: sBL/sLB
    __shared__ float sMu[U1c], spb0[U1c], splab[Uc];
    __shared__ int   slab[Uc];
    __shared__ float wmax[8], sMt[2], stb0[2];
    __shared__ int   sUlen, sLast;

    int b   = blockIdx.y;
    int t0  = blockIdx.x * 2;
    int tid = threadIdx.x;
    int lane = tid & 31, w = tid >> 5;

    // ---------------- Phase A ----------------
    int r = tid >> 7;                      // t-row 0..1
    int j = tid & 127;                     // float4 index within row
    const float* trow = trans + ((size_t)(b * Tc + t0 + r)) * Vc;
    float4 v = ((const float4*)trow)[j];

    float m = fmaxf(fmaxf(v.x, v.y), fmaxf(v.z, v.w));
#pragma unroll
    for (int o = 16; o; o >>= 1)
        m = fmaxf(m, __shfl_xor_sync(0xffffffffu, m, o));
    if (lane == 0) wmax[w] = m;

    // per-b small tables (no dependence on wmax)
    if (tid < U1c) { sMu[tid] = g_Mu[b * U1c + tid]; spb0[tid] = g_pb0[b * U1c + tid]; }
    if (tid >= 128 && tid < 128 + Uc) splab[tid - 128] = g_plab[b * Uc + (tid - 128)];
    if (tid >= 192 && tid < 192 + Uc) slab[tid - 192]  = labels[b * Uc + (tid - 192)];
    if (tid == 0) sUlen = label_lens[b];
    __syncthreads();

    m = fmaxf(fmaxf(wmax[4 * r], wmax[4 * r + 1]),
              fmaxf(wmax[4 * r + 2], wmax[4 * r + 3]));
    float4 e;
    e.x = __expf(v.x - m); e.y = __expf(v.y - m);
    e.z = __expf(v.z - m); e.w = __expf(v.w - m);
    ((float4*)dsmem)[r * 128 + j] = e;
    if (j == 0) { sMt[r] = m; stb0[r] = v.x; }
    __syncthreads();

    // ---------------- Phase B: warp-private u columns ----------------
    // a regs: 2 rows x 4 float4 (elements lane+32k of each row)
    float4 a[8];
#pragma unroll
    for (int k = 0; k < 4; ++k) {
        a[k]     = ((const float4*)dsmem)[lane + 32 * k];
        a[4 + k] = ((const float4*)dsmem)[128 + lane + 32 * k];
    }

    const float4* P = (const float4*)(g_expP + (size_t)b * U1c * Vc);
    int nu = (w == 0) ? 9 : 8;             // warp0 also covers u=64
    int u  = w;
    float4 p0 = P[u * 128 + lane],       p1 = P[u * 128 + lane + 32],
           p2 = P[u * 128 + lane + 64],  p3 = P[u * 128 + lane + 96];

    for (int i = 0; i < nu; ++i) {
        float4 q0 = p0, q1 = p1, q2 = p2, q3 = p3;
        int un = u + 8;
        if (i + 1 < nu) {
            p0 = P[un * 128 + lane];      p1 = P[un * 128 + lane + 32];
            p2 = P[un * 128 + lane + 64]; p3 = P[un * 128 + lane + 96];
        }

        float s0 = a[0].x*q0.x + a[0].y*q0.y + a[0].z*q0.z + a[0].w*q0.w
                 + a[1].x*q1.x + a[1].y*q1.y + a[1].z*q1.z + a[1].w*q1.w
                 + a[2].x*q2.x + a[2].y*q2.y + a[2].z*q2.z + a[2].w*q2.w
                 + a[3].x*q3.x + a[3].y*q3.y + a[3].z*q3.z + a[3].w*q3.w;
        float s1 = a[4].x*q0.x + a[4].y*q0.y + a[4].z*q0.z + a[4].w*q0.w
                 + a[5].x*q1.x + a[5].y*q1.y + a[5].z*q1.z + a[5].w*q1.w
                 + a[6].x*q2.x + a[6].y*q2.y + a[6].z*q2.z + a[6].w*q2.w
                 + a[7].x*q3.x + a[7].y*q3.y + a[7].z*q3.z + a[7].w*q3.w;

#pragma unroll
        for (int o = 16; o; o >>= 1) {
            s0 += __shfl_xor_sync(0xffffffffu, s0, o);
            s1 += __shfl_xor_sync(0xffffffffu, s1, o);
        }
        if (lane < 2) {
            float S = (lane == 0) ? s0 : s1;
            int t = t0 + lane;
            float logZ = sMt[lane] + sMu[u] + __logf(S);
            g_BL[((size_t)(b * Tc + t)) * U1c + u]
                = (stb0[lane] + spb0[u] - logZ) * LOG2E;
            if (u < Uc) {
                float lv = NEGV;
                if (u < sUlen) {
                    int l = slab[u];
                    float traw = __logf(dsmem[lane * Vc + l]) + sMt[lane];
                    lv = (traw + splab[u] - logZ) * LOG2E;
                }
                g_LB[((size_t)(b * Tc + t)) * U1c + u] = lv;
            }
        }
        u = un;
    }

    // ---------------- Phase C: last block of batch b runs the DP ----------------
    __threadfence();
    __syncthreads();
    if (tid == 0) {
        unsigned int old = atomicAdd(&g_bcnt[b], 1u);
        sLast = (old == (Tc / 2 - 1));
    }
    __syncthreads();
    if (!sLast) return;
    if (tid == 0) atomicExch(&g_bcnt[b], 0u);   // reset for next graph replay
    __threadfence();                             // acquire other blocks' BL/LB

    float* sBL = dsmem;                          // [Tc][65], log2 domain
    float* sLB = dsmem + Tc * U1c;               // [Tc][65], log2 domain
    {
        const float4* BLg = (const float4*)(g_BL + (size_t)b * Tc * U1c);
        const float4* LBg = (const float4*)(g_LB + (size_t)b * Tc * U1c);
        for (int i = tid; i < (Tc * U1c) / 4; i += 256) ((float4*)sBL)[i] = BLg[i];
        for (int i = tid; i < (Tc * U1c) / 4; i += 256) ((float4*)sLB)[i] = LBg[i];
    }
    __syncthreads();
    if (tid >= 32) return;

    // lane 0 owns u={0,1,2}; lane L>=1 owns u={2L+1, 2L+2}. u=0 is add-only.
    int L = tid;
    int tlen = act_lens[b];
    int ulen = sUlen;
    float v0 = 0.0f, v1 = 0.0f, v2 = 0.0f;       // lane 0
    float vA = 0.0f, vB = 0.0f;                  // lanes >= 1
    float last = 0.0f;                           // this lane's rightmost column value
    float cost = 0.0f;
    bool  have = false;
    int   uA = 2 * L + 1, uB = 2 * L + 2;

    for (int k = 0; k < Tc + 31; ++k) {
        float left = __shfl_up_sync(0xffffffffu, last, 1);  // left neighbor, same t
        int t = k - L;
        if (t >= 0 && t < Tc) {
            if (L == 0) {
                float n0, n1, n2;
                if (t == 0) {
                    n0 = 0.0f;
                    n1 = n0 + sLB[0];
                    n2 = n1 + sLB[1];
                } else {
                    const float* BLr = sBL + (t - 1) * U1c;
                    const float* LBr = sLB + t * U1c;
                    n0 = v0 + BLr[0];
                    n1 = lse2(v1 + BLr[1], n0 + LBr[0]);
                    n2 = lse2(v2 + BLr[2], n1 + LBr[1]);
                }
                v0 = n0; v1 = n1; v2 = n2; last = n2;
                if (t == tlen - 1) {
                    if      (ulen == 0) { cost = v0 + sBL[t * U1c + 0]; have = true; }
                    else if (ulen == 1) { cost = v1 + sBL[t * U1c + 1]; have = true; }
                    else if (ulen == 2) { cost = v2 + sBL[t * U1c + 2]; have = true; }
                }
            } else {
                float nA, nB;
                if (t == 0) {
                    nA = left + sLB[uA - 1];
                    nB = nA   + sLB[uB - 1];
                } else {
                    const float* BLr = sBL + (t - 1) * U1c;
                    const float* LBr = sLB + t * U1c;
                    float bA = vA + BLr[uA];
                    float lA = left + LBr[uA - 1];
                    nA = lse2(bA, lA);
                    float lbA = LBr[uA];
                    nB = lse3(vB + BLr[uB], bA + lbA, lA + lbA);
                }
                vA = nA; vB = nB; last = nB;
                if (t == tlen - 1) {
                    if      (ulen == uA) { cost = vA + sBL[t * U1c + uA]; have = true; }
                    else if (ulen == uB) { cost = vB + sBL[t * U1c + uB]; have = true; }
                }
            }
        }
    }

    if (have) {
        g_cost[b] = -cost * LN2F;
        __threadfence();
        unsigned int old = atomicAdd(&g_ticket, 1u);
        if (old == Bc - 1) {
            __threadfence();
            float s = 0.0f;
#pragma unroll
            for (int i = 0; i < Bc; ++i) s += g_cost[i];
            out[0] = s;
            atomicExch(&g_ticket, 0u);           // reset for next graph replay
        }
    }
}

// ------------------------------------------------------------------
extern "C" void kernel_launch(void* const* d_in, const int* in_sizes, int n_in,
                              void* d_out, int out_size)
{
    const float* trans      = (const float*)d_in[0];
    const float* pred       = (const float*)d_in[1];
    const int*   labels     = (const int*)  d_in[2];
    const int*   act_lens   = (const int*)  d_in[3];
    const int*   label_lens = (const int*)  d_in[4];
    float* out = (float*)d_out;

    const int dynSmem = 2 * Tc * U1c * sizeof(float);   // 66560 B (phase C tables)
    cudaFuncSetAttribute(k_main, cudaFuncAttributeMaxDynamicSharedMemorySize, dynSmem);

    k_prep_pred<<<Bc * U1c, 128>>>(pred, labels);
    k_main<<<dim3(Tc / 2, Bc), 256, dynSmem>>>(trans, labels, act_lens, label_lens, out);
}